// round 1
// baseline (speedup 1.0000x reference)
#include <cuda_runtime.h>
#include <math.h>

// Problem constants
#define NN      32768
#define KTOT    (3 * NN)           // 98304 rows of Y
#define NPART   296                // gram partial blocks (2 per SM on 148 SMs)
#define NTILES  (NN / 16)          // 2048 tiles of 16 nodes (48 Y-rows each)

__device__ __constant__ float c_TPN = 0.022097086912079608f;  // 1/sqrt(16*128)
__device__ __constant__ float c_ISV = 0.08838834764831845f;   // 1/sqrt(128)
#define EPSF 1e-5f

// ---------------- scratch (static device allocations only) ----------------
__device__ float g_part[NPART][128 * 128];  // gram partials (~19.4 MB)
__device__ float g_G[128 * 128];            // Gram matrix Y^T Y
__device__ float g_Wc1[128 * 128];          // tp_norm * sum_u w_u W_tp1[u]
__device__ float g_A[3][128 * 128];         // A0, A1, A2
__device__ float g_fn[3][128];              // per-channel second moments
__device__ float g_c[128];                  // final collapsed weight vector

// ---------------------------------------------------------------------------
// Kernel 1: partial Gram  G += B^T B  where B rows are Y[(n,m), v]
// Each block owns tiles (16 nodes = 48 k-rows) strided by NPART, accumulates
// an 8x8 register tile per thread (16x16 threads -> 128x128), writes its
// partial to g_part[blockIdx.x].
// ---------------------------------------------------------------------------
__global__ void __launch_bounds__(256, 2)
k_gram(const float* __restrict__ feat, const float* __restrict__ times) {
    __shared__ float B[48][132];  // +4 pad to dodge bank conflicts
    float acc[8][8];
#pragma unroll
    for (int i = 0; i < 8; i++)
#pragma unroll
        for (int j = 0; j < 8; j++) acc[i][j] = 0.f;

    const int tid = threadIdx.x;
    const int ty = tid >> 4;
    const int tx = tid & 15;

    for (int tile = blockIdx.x; tile < NTILES; tile += NPART) {
        __syncthreads();  // previous compute done before overwriting B
        const int node0 = tile * 16;
        // Load 16 nodes x 384 floats, deinterleave (v,m), scale by time_n.
#pragma unroll
        for (int i = 0; i < 6; i++) {
            const int f = tid + 256 * i;       // 0..1535
            const int r = f / 96;              // local node 0..15
            const int q = f - r * 96;          // float4 index within row
            const int n = node0 + r;
            const float4 val =
                *(const float4*)(feat + (size_t)n * 512 + 128 + 4 * q);
            const float tm = __ldg(times + n);
            const int j = 4 * q;
            B[r * 3 + (j    ) % 3][(j    ) / 3] = tm * val.x;
            B[r * 3 + (j + 1) % 3][(j + 1) / 3] = tm * val.y;
            B[r * 3 + (j + 2) % 3][(j + 2) / 3] = tm * val.z;
            B[r * 3 + (j + 3) % 3][(j + 3) / 3] = tm * val.w;
        }
        __syncthreads();
#pragma unroll 4
        for (int k = 0; k < 48; k++) {
            const float4 a0 = *(const float4*)&B[k][ty * 8];
            const float4 a1 = *(const float4*)&B[k][ty * 8 + 4];
            const float4 b0 = *(const float4*)&B[k][tx * 8];
            const float4 b1 = *(const float4*)&B[k][tx * 8 + 4];
            const float a[8] = {a0.x, a0.y, a0.z, a0.w, a1.x, a1.y, a1.z, a1.w};
            const float b[8] = {b0.x, b0.y, b0.z, b0.w, b1.x, b1.y, b1.z, b1.w};
#pragma unroll
            for (int i = 0; i < 8; i++)
#pragma unroll
                for (int j = 0; j < 8; j++)
                    acc[i][j] = fmaf(a[i], b[j], acc[i][j]);
        }
    }

    float* outp = g_part[blockIdx.x];
#pragma unroll
    for (int i = 0; i < 8; i++)
#pragma unroll
        for (int j = 0; j < 8; j++)
            outp[(ty * 8 + i) * 128 + tx * 8 + j] = acc[i][j];
}

// Deterministic reduction of partials into g_G.
__global__ void k_greduce() {
    const int i = blockIdx.x * blockDim.x + threadIdx.x;  // 0..16383
    float s = 0.f;
    for (int p = 0; p < NPART; p++) s += g_part[p][i];
    g_G[i] = s;
}

// Wc1[v,o] = tp_norm * sum_u W_time[u] * W_tp1[u,v,o]
__global__ void k_wc1(const float* __restrict__ W_time,
                      const float* __restrict__ W_tp1) {
    const int v = blockIdx.x, o = threadIdx.x;
    float acc = 0.f;
#pragma unroll
    for (int u = 0; u < 16; u++)
        acc = fmaf(W_time[u], W_tp1[u * 16384 + v * 128 + o], acc);
    g_Wc1[v * 128 + o] = acc * c_TPN;
}

// A_stage = (A_prev ⊙ d_{stage-1}) @ Wv[stage] * inv_sqrt_v
// stage 0: A_prev = Wc1, no d.
__global__ void k_layer(int stage, const float* __restrict__ Wv_all,
                        const float* __restrict__ gamma_v) {
    const float* Ain = (stage == 0) ? g_Wc1 : g_A[stage - 1];
    const float* W = Wv_all + stage * 16384;
    float* Aout = g_A[stage];

    __shared__ float ad[128];
    const int v = blockIdx.x, o = threadIdx.x;
    float x = Ain[v * 128 + o];
    if (stage > 0)
        x *= gamma_v[(stage - 1) * 128 + o] /
             sqrtf(g_fn[stage - 1][o] + EPSF);
    ad[o] = x;
    __syncthreads();
    float acc = 0.f;
#pragma unroll 8
    for (int w = 0; w < 128; w++)
        acc = fmaf(ad[w], W[w * 128 + o], acc);
    Aout[v * 128 + o] = acc * c_ISV;
}

// fn[stage][o] = (1/3N) * a_o^T G a_o, a_o = A[:,o]
__global__ void k_fn(int stage) {
    const float* A = g_A[stage];
    const int o = blockIdx.x, t = threadIdx.x;
    __shared__ float a[128];
    __shared__ float red[128];
    a[t] = A[t * 128 + o];
    __syncthreads();
    float p = 0.f;
#pragma unroll 8
    for (int v = 0; v < 128; v++)
        p = fmaf(a[v], g_G[v * 128 + t], p);
    red[t] = p * a[t];
    __syncthreads();
    for (int s = 64; s > 0; s >>= 1) {
        if (t < s) red[t] += red[t + s];
        __syncthreads();
    }
    if (t == 0) g_fn[stage][o] = red[0] / (float)KTOT;
}

// c[v] = inv_sqrt_v * sum_o A2[v,o] * d2[o] * W_r[o]
__global__ void k_cvec(const float* __restrict__ gamma_v,
                       const float* __restrict__ W_r) {
    const int v = threadIdx.x;  // 128 threads, 1 block
    __shared__ float dw[128];
    dw[v] = gamma_v[2 * 128 + v] / sqrtf(g_fn[2][v] + EPSF) * W_r[v] * c_ISV;
    __syncthreads();
    float acc = 0.f;
#pragma unroll 8
    for (int o = 0; o < 128; o++)
        acc = fmaf(g_A[2][v * 128 + o], dw[o], acc);
    g_c[v] = acc;
}

// out[n,m] = time_n * sum_v x_v[n,v,m] * c[v]   (one warp per node)
__global__ void k_out(const float* __restrict__ feat,
                      const float* __restrict__ times,
                      float* __restrict__ out) {
    const int gw = (blockIdx.x * blockDim.x + threadIdx.x) >> 5;
    const int lane = threadIdx.x & 31;
    if (gw >= NN) return;
    const float4* p = (const float4*)(feat + (size_t)gw * 512 + 128);
    float s0 = 0.f, s1 = 0.f, s2 = 0.f;
#pragma unroll
    for (int i = 0; i < 3; i++) {
        const int f4 = lane + 32 * i;
        const float4 x = p[f4];
        const int j = 4 * f4;
        const float comp[4] = {x.x, x.y, x.z, x.w};
#pragma unroll
        for (int e = 0; e < 4; e++) {
            const int jj = j + e;
            const float pr = comp[e] * g_c[jj / 3];
            const int m = jj % 3;
            s0 += (m == 0) ? pr : 0.f;
            s1 += (m == 1) ? pr : 0.f;
            s2 += (m == 2) ? pr : 0.f;
        }
    }
#pragma unroll
    for (int off = 16; off > 0; off >>= 1) {
        s0 += __shfl_xor_sync(0xffffffffu, s0, off);
        s1 += __shfl_xor_sync(0xffffffffu, s1, off);
        s2 += __shfl_xor_sync(0xffffffffu, s2, off);
    }
    if (lane == 0) {
        const float tm = times[gw];
        out[gw * 3 + 0] = tm * s0;
        out[gw * 3 + 1] = tm * s1;
        out[gw * 3 + 2] = tm * s2;
    }
}

// ---------------------------------------------------------------------------
extern "C" void kernel_launch(void* const* d_in, const int* in_sizes, int n_in,
                              void* d_out, int out_size) {
    const float* feat    = (const float*)d_in[0];   // (N, 512)
    const float* times   = (const float*)d_in[1];   // (N, 1)
    const float* W_time  = (const float*)d_in[2];   // (1, 16)
    // d_in[3] = W_tp0 (dead: s-branch unused)
    const float* W_tp1   = (const float*)d_in[4];   // (16, 128, 128)
    // d_in[5] = Ws (dead), [7] gamma_s (dead), [8] beta_s (dead)
    const float* Wv      = (const float*)d_in[6];   // (3, 128, 128)
    const float* gamma_v = (const float*)d_in[9];   // (3, 128)
    const float* W_r     = (const float*)d_in[10];  // (128, 1)
    float* out = (float*)d_out;                     // (N, 3)

    k_gram<<<NPART, 256>>>(feat, times);
    k_greduce<<<64, 256>>>();
    k_wc1<<<128, 128>>>(W_time, W_tp1);

    k_layer<<<128, 128>>>(0, Wv, gamma_v);
    k_fn<<<128, 128>>>(0);
    k_layer<<<128, 128>>>(1, Wv, gamma_v);
    k_fn<<<128, 128>>>(1);
    k_layer<<<128, 128>>>(2, Wv, gamma_v);
    k_fn<<<128, 128>>>(2);
    k_cvec<<<1, 128>>>(gamma_v, W_r);

    k_out<<<(NN * 32) / 256, 256>>>(feat, times, out);
}